// round 2
// baseline (speedup 1.0000x reference)
#include <cuda_runtime.h>
#include <math.h>

// Problem constants
#define Bc   2
#define Lc   2048
#define Dc   1024
#define Hc   16
#define HDc  64
#define NT   (Bc*Lc)     // 4096 tokens
#define BHc  (Bc*Hc)     // 32 (batch*heads)

// ---------------- scratch (device globals; no allocation allowed) ----------
__device__ float g_Q [BHc*Lc*HDc];   // [bh][l][hd]
__device__ float g_K [BHc*Lc*HDc];
__device__ float g_V [BHc*Lc*HDc];
__device__ float g_G [(size_t)NT*Dc];   // gate, [token][d]
__device__ float g_AO[(size_t)NT*Dc];   // attn out * gate, [token][d]
__device__ int   g_mask[NT];            // 1 = masked (exclude)

// ---------------- mask decode (robust to bool8 / int32 / float32) ----------
__global__ void mask_decode_kernel(const unsigned char* __restrict__ raw) {
    __shared__ int cnt[4];
    int tid = threadIdx.x;
    if (tid < 4) cnt[tid] = 0;
    __syncthreads();
    // Only the first NT bytes are guaranteed in-bounds for every candidate dtype.
    for (int i = tid; i < NT; i += blockDim.x)
        if (raw[i]) atomicAdd(&cnt[i & 3], 1);
    __syncthreads();
    int c0 = cnt[0], c1 = cnt[1], c2 = cnt[2], c3 = cnt[3];
    int mode; // 0 = bool8/int8, 1 = int32, 2 = float32
    if (c0 > 0 && c1 == 0 && c2 == 0 && c3 == 0)      mode = 1;  // only word-low bytes set
    else if ((c2 > 0 || c3 > 0) && c0 == 0 && c1 == 0) mode = 2; // 1.0f = 00 00 80 3f
    else                                               mode = 0;
    for (int i = tid; i < NT; i += blockDim.x) {
        int v;
        if (mode == 0)      v = (raw[i] != 0);
        else if (mode == 1) v = (((const int*)raw)[i] != 0);
        else                v = (((const float*)raw)[i] != 0.0f);
        g_mask[i] = v;
    }
}

// ---------------- fused 4-way projection GEMM ------------------------------
// out[m,n] = A[m,:] . W[n,:] + b[n]; z selects (A, W, b, epilogue).
// z=0: Q -> g_Q (head layout)   z=1: K -> g_K   z=2: V -> g_V
// z=3: gate = sigmoid -> g_G (token-major)
__global__ __launch_bounds__(256) void proj_gemm_kernel(
    const float* __restrict__ query, const float* __restrict__ key_in,
    const float* __restrict__ value,
    const float* __restrict__ Wq, const float* __restrict__ bq,
    const float* __restrict__ Wk, const float* __restrict__ bk,
    const float* __restrict__ Wv, const float* __restrict__ bv,
    const float* __restrict__ Wg, const float* __restrict__ bg)
{
    int z = blockIdx.z;
    const float* A; const float* W; const float* bias;
    if      (z == 0) { A = query;  W = Wq; bias = bq; }
    else if (z == 1) { A = key_in; W = Wk; bias = bk; }
    else if (z == 2) { A = value;  W = Wv; bias = bv; }
    else             { A = query;  W = Wg; bias = bg; }

    const int m0 = blockIdx.y * 64;
    const int n0 = blockIdx.x * 64;

    __shared__ float As[16][64];   // [k][m]
    __shared__ float Bs[16][64];   // [k][n]

    const int tid  = threadIdx.x;
    const int ty   = tid >> 4;       // 0..15
    const int tx   = tid & 15;       // 0..15
    const int lrow = tid >> 2;       // 0..63
    const int lk   = (tid & 3) << 2; // 0,4,8,12

    const float* Ap = A + (size_t)(m0 + lrow) * Dc + lk;
    const float* Wp = W + (size_t)(n0 + lrow) * Dc + lk;

    float acc[4][4];
    #pragma unroll
    for (int i = 0; i < 4; i++)
        #pragma unroll
        for (int j = 0; j < 4; j++) acc[i][j] = 0.f;

    for (int k0 = 0; k0 < Dc; k0 += 16) {
        float4 a4 = *(const float4*)(Ap + k0);
        float4 w4 = *(const float4*)(Wp + k0);
        __syncthreads();
        As[lk+0][lrow] = a4.x; As[lk+1][lrow] = a4.y;
        As[lk+2][lrow] = a4.z; As[lk+3][lrow] = a4.w;
        Bs[lk+0][lrow] = w4.x; Bs[lk+1][lrow] = w4.y;
        Bs[lk+2][lrow] = w4.z; Bs[lk+3][lrow] = w4.w;
        __syncthreads();
        #pragma unroll
        for (int kk = 0; kk < 16; kk++) {
            float4 ra4 = *(const float4*)&As[kk][ty << 2];
            float4 rb4 = *(const float4*)&Bs[kk][tx << 2];
            float ra[4] = {ra4.x, ra4.y, ra4.z, ra4.w};
            float rb[4] = {rb4.x, rb4.y, rb4.z, rb4.w};
            #pragma unroll
            for (int i = 0; i < 4; i++)
                #pragma unroll
                for (int j = 0; j < 4; j++)
                    acc[i][j] += ra[i] * rb[j];
        }
    }

    #pragma unroll
    for (int i = 0; i < 4; i++) {
        int m = m0 + (ty << 2) + i;
        int b = m >> 11;          // / Lc
        int l = m & (Lc - 1);
        #pragma unroll
        for (int j = 0; j < 4; j++) {
            int n = n0 + (tx << 2) + j;
            float v = acc[i][j] + bias[n];
            if (z == 3) {
                g_G[(size_t)m * Dc + n] = 1.f / (1.f + __expf(-v));
            } else {
                int h = n >> 6, hd = n & 63;
                size_t addr = ((size_t)(b * Hc + h) * Lc + l) * HDc + hd;
                if (z == 0)      g_Q[addr] = v;
                else if (z == 1) g_K[addr] = v;
                else             g_V[addr] = v;
            }
        }
    }
}

// ---------------- RoPE (in place on g_Q and g_K) ---------------------------
__global__ void rope_kernel(const float* __restrict__ cosb,
                            const float* __restrict__ sinb)
{
    const int NP = BHc * Lc * 32;       // pairs per tensor
    int idx = blockIdx.x * blockDim.x + threadIdx.x;
    if (idx >= 2 * NP) return;
    float* X = (idx < NP) ? g_Q : g_K;
    int p   = (idx < NP) ? idx : idx - NP;
    int hd  = p & 31;
    int row = p >> 5;                   // bh*L + l
    int l   = row & (Lc - 1);
    size_t base = (size_t)row * 64;
    float x1 = X[base + hd];
    float x2 = X[base + hd + 32];
    float c1 = cosb[l * 64 + hd],      s1 = sinb[l * 64 + hd];
    float c2 = cosb[l * 64 + hd + 32], s2 = sinb[l * 64 + hd + 32];
    X[base + hd]      = x1 * c1 - x2 * s1;
    X[base + hd + 32] = x2 * c2 + x1 * s2;
}

// ---------------- flash attention + gate fuse ------------------------------
#define STR 68                     // padded row stride (68*4B = 272B, 16B-aligned)
#define SM_QS 0
#define SM_KS (64*STR)
#define SM_VS (2*64*STR)
#define SM_PS (2*64*STR + 64*64)
#define SM_MK (3*64*STR + 64*64)
#define ATTN_SMEM ((3*64*STR + 64*64 + 64) * 4)

__global__ __launch_bounds__(256) void attn_kernel()
{
    extern __shared__ float sm[];
    float* Qs = sm + SM_QS;   // [d][row], stride STR
    float* Ks = sm + SM_KS;   // [d][col], stride STR
    float* Vs = sm + SM_VS;   // [k][dim], stride 64
    float* Ps = sm + SM_PS;   // [row][k], stride STR
    float* mk = sm + SM_MK;   // [64] additive mask (0 or -1e30)

    const int qt = blockIdx.x;         // q tile (0..31)
    const int bh = blockIdx.y;         // 0..31
    const int b  = bh >> 4;
    const int h  = bh & 15;
    const int tid = threadIdx.x;
    const int ty = tid >> 4, tx = tid & 15;

    // load Q tile (transposed into [d][row])
    const float* Qg = g_Q + ((size_t)bh * Lc + qt * 64) * 64;
    for (int i = tid; i < 4096; i += 256) {
        int r = i >> 6, d = i & 63;
        Qs[d * STR + r] = Qg[i];
    }

    float m_i[4], l_i[4], O[4][4];
    #pragma unroll
    for (int i = 0; i < 4; i++) {
        m_i[i] = -1e30f; l_i[i] = 0.f;
        #pragma unroll
        for (int j = 0; j < 4; j++) O[i][j] = 0.f;
    }

    const int* maskb = g_mask + b * Lc;

    for (int kt = 0; kt < 32; kt++) {
        __syncthreads();   // prior iteration's Ks/Vs/Ps reads are done
        const float* Kg = g_K + ((size_t)bh * Lc + kt * 64) * 64;
        const float* Vg = g_V + ((size_t)bh * Lc + kt * 64) * 64;
        for (int i = tid; i < 4096; i += 256) {
            int r = i >> 6, d = i & 63;
            Ks[d * STR + r] = Kg[i];
            Vs[i] = Vg[i];
        }
        if (tid < 64) mk[tid] = maskb[kt * 64 + tid] ? -1e30f : 0.f;
        __syncthreads();

        // S = Q . K^T
        float S[4][4];
        #pragma unroll
        for (int i = 0; i < 4; i++)
            #pragma unroll
            for (int j = 0; j < 4; j++) S[i][j] = 0.f;
        #pragma unroll 8
        for (int d = 0; d < 64; d++) {
            float4 qa4 = *(const float4*)&Qs[d * STR + (ty << 2)];
            float4 kb4 = *(const float4*)&Ks[d * STR + (tx << 2)];
            float qa[4] = {qa4.x, qa4.y, qa4.z, qa4.w};
            float kb[4] = {kb4.x, kb4.y, kb4.z, kb4.w};
            #pragma unroll
            for (int i = 0; i < 4; i++)
                #pragma unroll
                for (int j = 0; j < 4; j++)
                    S[i][j] += qa[i] * kb[j];
        }

        // scale + additive mask
        float mcol[4];
        #pragma unroll
        for (int j = 0; j < 4; j++) mcol[j] = mk[(tx << 2) + j];
        #pragma unroll
        for (int i = 0; i < 4; i++)
            #pragma unroll
            for (int j = 0; j < 4; j++)
                S[i][j] = S[i][j] * 0.125f + mcol[j];

        // online softmax update
        float alpha[4];
        #pragma unroll
        for (int i = 0; i < 4; i++) {
            float rm = fmaxf(fmaxf(S[i][0], S[i][1]), fmaxf(S[i][2], S[i][3]));
            #pragma unroll
            for (int off = 8; off >= 1; off >>= 1)
                rm = fmaxf(rm, __shfl_xor_sync(0xffffffffu, rm, off));
            float mn = fmaxf(m_i[i], rm);
            float rs = 0.f;
            #pragma unroll
            for (int j = 0; j < 4; j++) {
                float p = (S[i][j] < -1e29f) ? 0.f : __expf(S[i][j] - mn);
                S[i][j] = p;
                rs += p;
            }
            #pragma unroll
            for (int off = 8; off >= 1; off >>= 1)
                rs += __shfl_xor_sync(0xffffffffu, rs, off);
            alpha[i] = __expf(m_i[i] - mn);
            l_i[i]   = l_i[i] * alpha[i] + rs;
            m_i[i]   = mn;
        }

        // P to shared; rescale O
        #pragma unroll
        for (int i = 0; i < 4; i++) {
            float4 p4 = make_float4(S[i][0], S[i][1], S[i][2], S[i][3]);
            *(float4*)&Ps[((ty << 2) + i) * STR + (tx << 2)] = p4;
            #pragma unroll
            for (int j = 0; j < 4; j++) O[i][j] *= alpha[i];
        }
        __syncthreads();

        // O += P . V
        #pragma unroll 8
        for (int kk = 0; kk < 64; kk++) {
            float4 vb4 = *(const float4*)&Vs[kk * 64 + (tx << 2)];
            float vb[4] = {vb4.x, vb4.y, vb4.z, vb4.w};
            float pv[4];
            #pragma unroll
            for (int i = 0; i < 4; i++)
                pv[i] = Ps[((ty << 2) + i) * STR + kk];
            #pragma unroll
            for (int i = 0; i < 4; i++)
                #pragma unroll
                for (int j = 0; j < 4; j++)
                    O[i][j] += pv[i] * vb[j];
        }
    }

    // epilogue: normalize, nan-guard, gate, store token-major
    #pragma unroll
    for (int i = 0; i < 4; i++) {
        int lq = qt * 64 + (ty << 2) + i;
        size_t tok = (size_t)b * Lc + lq;
        float inv = (l_i[i] > 0.f) ? (1.f / l_i[i]) : 0.f;
        #pragma unroll
        for (int j = 0; j < 4; j++) {
            int n = h * 64 + (tx << 2) + j;
            float g = g_G[tok * Dc + n];
            g_AO[tok * Dc + n] = O[i][j] * inv * g;
        }
    }
}

// ---------------- output projection GEMM -----------------------------------
__global__ __launch_bounds__(256) void out_gemm_kernel(
    const float* __restrict__ Wo, const float* __restrict__ bo,
    float* __restrict__ out)
{
    const int m0 = blockIdx.y * 64;
    const int n0 = blockIdx.x * 64;
    __shared__ float As[16][64];
    __shared__ float Bs[16][64];
    const int tid  = threadIdx.x;
    const int ty   = tid >> 4, tx = tid & 15;
    const int lrow = tid >> 2;
    const int lk   = (tid & 3) << 2;
    const float* Ap = g_AO + (size_t)(m0 + lrow) * Dc + lk;
    const float* Wp = Wo   + (size_t)(n0 + lrow) * Dc + lk;

    float acc[4][4];
    #pragma unroll
    for (int i = 0; i < 4; i++)
        #pragma unroll
        for (int j = 0; j < 4; j++) acc[i][j] = 0.f;

    for (int k0 = 0; k0 < Dc; k0 += 16) {
        float4 a4 = *(const float4*)(Ap + k0);
        float4 w4 = *(const float4*)(Wp + k0);
        __syncthreads();
        As[lk+0][lrow] = a4.x; As[lk+1][lrow] = a4.y;
        As[lk+2][lrow] = a4.z; As[lk+3][lrow] = a4.w;
        Bs[lk+0][lrow] = w4.x; Bs[lk+1][lrow] = w4.y;
        Bs[lk+2][lrow] = w4.z; Bs[lk+3][lrow] = w4.w;
        __syncthreads();
        #pragma unroll
        for (int kk = 0; kk < 16; kk++) {
            float4 ra4 = *(const float4*)&As[kk][ty << 2];
            float4 rb4 = *(const float4*)&Bs[kk][tx << 2];
            float ra[4] = {ra4.x, ra4.y, ra4.z, ra4.w};
            float rb[4] = {rb4.x, rb4.y, rb4.z, rb4.w};
            #pragma unroll
            for (int i = 0; i < 4; i++)
                #pragma unroll
                for (int j = 0; j < 4; j++)
                    acc[i][j] += ra[i] * rb[j];
        }
    }

    #pragma unroll
    for (int i = 0; i < 4; i++) {
        int m = m0 + (ty << 2) + i;
        #pragma unroll
        for (int j = 0; j < 4; j++) {
            int n = n0 + (tx << 2) + j;
            out[(size_t)m * Dc + n] = acc[i][j] + bo[n];
        }
    }
}

// ---------------- launch ----------------------------------------------------
extern "C" void kernel_launch(void* const* d_in, const int* in_sizes, int n_in,
                              void* d_out, int out_size)
{
    const float* query   = (const float*)d_in[0];
    const float* key_in  = (const float*)d_in[1];
    const float* value   = (const float*)d_in[2];
    const unsigned char* maskraw = (const unsigned char*)d_in[3];
    const float* rope_cos = (const float*)d_in[4];
    const float* rope_sin = (const float*)d_in[5];
    const float* Wq = (const float*)d_in[6];
    const float* bq = (const float*)d_in[7];
    const float* Wk = (const float*)d_in[8];
    const float* bk = (const float*)d_in[9];
    const float* Wv = (const float*)d_in[10];
    const float* bv = (const float*)d_in[11];
    const float* Wg = (const float*)d_in[12];
    const float* bg = (const float*)d_in[13];
    const float* Wo = (const float*)d_in[14];
    const float* bo = (const float*)d_in[15];
    float* out = (float*)d_out;

    (void)in_sizes; (void)n_in; (void)out_size;

    mask_decode_kernel<<<1, 1024>>>(maskraw);

    dim3 pg(Dc / 64, NT / 64, 4);          // (16, 64, 4)
    proj_gemm_kernel<<<pg, 256>>>(query, key_in, value,
                                  Wq, bq, Wk, bk, Wv, bv, Wg, bg);

    int rope_threads = 2 * BHc * Lc * 32;  // 4.19M
    rope_kernel<<<rope_threads / 256, 256>>>(rope_cos, rope_sin);

    cudaFuncSetAttribute(attn_kernel,
                         cudaFuncAttributeMaxDynamicSharedMemorySize, ATTN_SMEM);
    attn_kernel<<<dim3(Lc / 64, BHc), 256, ATTN_SMEM>>>();

    out_gemm_kernel<<<dim3(Dc / 64, NT / 64), 256>>>(Wo, bo, out);
}

// round 4
// speedup vs baseline: 2.6598x; 2.6598x over previous
#include <cuda_runtime.h>
#include <math.h>
#include <stdint.h>

// Problem constants
#define Bc   2
#define Lc   2048
#define Dc   1024
#define Hc   16
#define HDc  64
#define NT   (Bc*Lc)     // 4096 tokens
#define BHc  (Bc*Hc)     // 32 (batch*heads)

// ---------------- scratch (device globals; no allocation allowed) ----------
__device__ float g_Q [BHc*Lc*HDc];   // [bh][l][hd]
__device__ float g_K [BHc*Lc*HDc];
__device__ float g_V [BHc*Lc*HDc];
__device__ float g_G [(size_t)NT*Dc];   // gate, [token][d]
__device__ float g_AO[(size_t)NT*Dc];   // attn out * gate, [token][d]
__device__ int   g_mask[NT];            // 1 = masked (exclude)

// ---------------- tf32 helpers ---------------------------------------------
__device__ __forceinline__ uint32_t f2tf(float x) {
    uint32_t u;
    asm("cvt.rna.tf32.f32 %0, %1;" : "=r"(u) : "f"(x));
    return u;
}
__device__ __forceinline__ float f2tf_f(float x) {
    return __uint_as_float(f2tf(x));
}
__device__ __forceinline__ void mma_tf32(
    float& d0, float& d1, float& d2, float& d3,
    uint32_t a0, uint32_t a1, uint32_t a2, uint32_t a3,
    uint32_t b0, uint32_t b1)
{
    asm volatile(
        "mma.sync.aligned.m16n8k8.row.col.f32.tf32.tf32.f32 "
        "{%0,%1,%2,%3}, {%4,%5,%6,%7}, {%8,%9}, {%0,%1,%2,%3};\n"
        : "+f"(d0), "+f"(d1), "+f"(d2), "+f"(d3)
        : "r"(a0), "r"(a1), "r"(a2), "r"(a3), "r"(b0), "r"(b1));
}

// ---------------- mask decode (robust to bool8 / int32 / float32) ----------
__global__ void mask_decode_kernel(const unsigned char* __restrict__ raw) {
    __shared__ int cnt[4];
    int tid = threadIdx.x;
    if (tid < 4) cnt[tid] = 0;
    __syncthreads();
    for (int i = tid; i < NT; i += blockDim.x)
        if (raw[i]) atomicAdd(&cnt[i & 3], 1);
    __syncthreads();
    int c0 = cnt[0], c1 = cnt[1], c2 = cnt[2], c3 = cnt[3];
    int mode; // 0 = bool8/int8, 1 = int32, 2 = float32
    if (c0 > 0 && c1 == 0 && c2 == 0 && c3 == 0)       mode = 1;
    else if ((c2 > 0 || c3 > 0) && c0 == 0 && c1 == 0) mode = 2;
    else                                               mode = 0;
    for (int i = tid; i < NT; i += blockDim.x) {
        int v;
        if (mode == 0)      v = (raw[i] != 0);
        else if (mode == 1) v = (((const int*)raw)[i] != 0);
        else                v = (((const float*)raw)[i] != 0.0f);
        g_mask[i] = v;
    }
}

// ---------------- TF32 tensor-core projection GEMM -------------------------
// Block tile 128(m) x 64(n), k-chunk 16. 8 warps, each 32x32 (2 mtiles x 4 ntiles).
// z=0: Q   z=1: K   z=2: V  (head-layout scatter)   z=3: gate (sigmoid, token-major)
#define GPAD 20

__global__ __launch_bounds__(256) void proj_gemm_tc(
    const float* __restrict__ query, const float* __restrict__ key_in,
    const float* __restrict__ value,
    const float* __restrict__ Wq, const float* __restrict__ bq,
    const float* __restrict__ Wk, const float* __restrict__ bk,
    const float* __restrict__ Wv, const float* __restrict__ bv,
    const float* __restrict__ Wg, const float* __restrict__ bg)
{
    const int z = blockIdx.z;
    const float* A; const float* W; const float* bias;
    if      (z == 0) { A = query;  W = Wq; bias = bq; }
    else if (z == 1) { A = key_in; W = Wk; bias = bk; }
    else if (z == 2) { A = value;  W = Wv; bias = bv; }
    else             { A = query;  W = Wg; bias = bg; }

    const int m0 = blockIdx.y * 128;
    const int n0 = blockIdx.x * 64;

    __shared__ float As[128 * GPAD];   // [m][k], stride 20
    __shared__ float Bs[64  * GPAD];   // [n][k], stride 20

    const int tid  = threadIdx.x;
    const int warp = tid >> 5;
    const int lane = tid & 31;
    const int q    = lane >> 2;      // group id 0..7
    const int tq   = lane & 3;       // thread in group 0..3
    const int warpM0 = (warp >> 1) * 32;
    const int warpN0 = (warp & 1) * 32;

    float acc[2][4][4];
    #pragma unroll
    for (int mt = 0; mt < 2; mt++)
        #pragma unroll
        for (int nt = 0; nt < 4; nt++)
            #pragma unroll
            for (int e = 0; e < 4; e++) acc[mt][nt][e] = 0.f;

    for (int k0 = 0; k0 < Dc; k0 += 16) {
        __syncthreads();
        // A tile: 128x16 = 512 float4, 2 per thread
        #pragma unroll
        for (int i = 0; i < 2; i++) {
            int f = tid + i * 256;
            int m = f >> 2, kq = f & 3;
            float4 v = *(const float4*)(A + (size_t)(m0 + m) * Dc + k0 + kq * 4);
            v.x = f2tf_f(v.x); v.y = f2tf_f(v.y); v.z = f2tf_f(v.z); v.w = f2tf_f(v.w);
            *(float4*)&As[m * GPAD + kq * 4] = v;
        }
        // B tile: 64x16 = 256 float4, 1 per thread
        {
            int n = tid >> 2, kq = tid & 3;
            float4 v = *(const float4*)(W + (size_t)(n0 + n) * Dc + k0 + kq * 4);
            v.x = f2tf_f(v.x); v.y = f2tf_f(v.y); v.z = f2tf_f(v.z); v.w = f2tf_f(v.w);
            *(float4*)&Bs[n * GPAD + kq * 4] = v;
        }
        __syncthreads();

        #pragma unroll
        for (int ks = 0; ks < 16; ks += 8) {
            uint32_t af[2][4];
            #pragma unroll
            for (int mt = 0; mt < 2; mt++) {
                int r = warpM0 + mt * 16 + q;
                af[mt][0] = __float_as_uint(As[r       * GPAD + ks     + tq]);
                af[mt][1] = __float_as_uint(As[(r + 8) * GPAD + ks     + tq]);
                af[mt][2] = __float_as_uint(As[r       * GPAD + ks + 4 + tq]);
                af[mt][3] = __float_as_uint(As[(r + 8) * GPAD + ks + 4 + tq]);
            }
            #pragma unroll
            for (int nt = 0; nt < 4; nt++) {
                int n = warpN0 + nt * 8 + q;
                uint32_t b0 = __float_as_uint(Bs[n * GPAD + ks     + tq]);
                uint32_t b1 = __float_as_uint(Bs[n * GPAD + ks + 4 + tq]);
                #pragma unroll
                for (int mt = 0; mt < 2; mt++)
                    mma_tf32(acc[mt][nt][0], acc[mt][nt][1], acc[mt][nt][2], acc[mt][nt][3],
                             af[mt][0], af[mt][1], af[mt][2], af[mt][3], b0, b1);
            }
        }
    }

    // epilogue
    #pragma unroll
    for (int mt = 0; mt < 2; mt++)
        #pragma unroll
        for (int nt = 0; nt < 4; nt++)
            #pragma unroll
            for (int e = 0; e < 4; e++) {
                int row = m0 + warpM0 + mt * 16 + q + ((e >> 1) ? 8 : 0);
                int col = n0 + warpN0 + nt * 8 + tq * 2 + (e & 1);
                float v = acc[mt][nt][e] + bias[col];
                if (z == 3) {
                    g_G[(size_t)row * Dc + col] = 1.f / (1.f + __expf(-v));
                } else {
                    int b = row >> 11, l = row & (Lc - 1);
                    int h = col >> 6, hd = col & 63;
                    size_t addr = ((size_t)(b * Hc + h) * Lc + l) * HDc + hd;
                    if (z == 0)      g_Q[addr] = v;
                    else if (z == 1) g_K[addr] = v;
                    else             g_V[addr] = v;
                }
            }
}

// ---------------- RoPE (in place on g_Q and g_K) ---------------------------
__global__ void rope_kernel(const float* __restrict__ cosb,
                            const float* __restrict__ sinb)
{
    const int NP = BHc * Lc * 32;
    int idx = blockIdx.x * blockDim.x + threadIdx.x;
    if (idx >= 2 * NP) return;
    float* X = (idx < NP) ? g_Q : g_K;
    int p   = (idx < NP) ? idx : idx - NP;
    int hd  = p & 31;
    int row = p >> 5;
    int l   = row & (Lc - 1);
    size_t base = (size_t)row * 64;
    float x1 = X[base + hd];
    float x2 = X[base + hd + 32];
    float c1 = cosb[l * 64 + hd],      s1 = sinb[l * 64 + hd];
    float c2 = cosb[l * 64 + hd + 32], s2 = sinb[l * 64 + hd + 32];
    X[base + hd]      = x1 * c1 - x2 * s1;
    X[base + hd + 32] = x2 * c2 + x1 * s2;
}

// ---------------- TF32 tensor-core flash attention + gate fuse -------------
// q-tile 128 rows; 8 warps, each owns 16 q-rows x all 64 cols.
// smem strides picked for conflict-free fragment LDS.
#define QSTR 68
#define VSTR 72
#define AT_QS 0
#define AT_KS (128*QSTR)                   // 8704
#define AT_VS (AT_KS + 64*QSTR)            // 13056
#define AT_PS (AT_VS + 64*VSTR)            // 17664
#define AT_MK (AT_PS + 128*QSTR)           // 26368
#define ATTN_SMEM ((AT_MK + 64) * 4)       // 105728 bytes

__global__ __launch_bounds__(256) void attn_tc_kernel()
{
    extern __shared__ float sm[];
    float* Qs = sm + AT_QS;   // [128][QSTR]
    float* Ks = sm + AT_KS;   // [64][QSTR]
    float* Vs = sm + AT_VS;   // [64][VSTR]
    float* Ps = sm + AT_PS;   // [128][QSTR]
    float* mk = sm + AT_MK;   // [64]

    const int qt  = blockIdx.x;        // 0..15 (tiles of 128 q rows)
    const int bh  = blockIdx.y;        // 0..31
    const int b   = bh >> 4;
    const int h   = bh & 15;
    const int tid = threadIdx.x;
    const int warp = tid >> 5;
    const int lane = tid & 31;
    const int q    = lane >> 2;
    const int tq   = lane & 3;
    const int warpM0 = warp * 16;

    // ---- prologue: Q tile -> smem (tf32-rounded) ----
    const float* Qg = g_Q + ((size_t)bh * Lc + qt * 128) * 64;
    #pragma unroll
    for (int it = 0; it < 8; it++) {
        int f = tid + it * 256;        // float4 index, 2048 total
        int m = f >> 4, cq = f & 15;
        float4 v = *(const float4*)(Qg + m * 64 + cq * 4);
        v.x = f2tf_f(v.x); v.y = f2tf_f(v.y); v.z = f2tf_f(v.z); v.w = f2tf_f(v.w);
        *(float4*)&Qs[m * QSTR + cq * 4] = v;
    }

    float O[8][4];
    #pragma unroll
    for (int nt = 0; nt < 8; nt++)
        #pragma unroll
        for (int e = 0; e < 4; e++) O[nt][e] = 0.f;
    float m0r = -1e30f, m1r = -1e30f, l0r = 0.f, l1r = 0.f;

    const int* maskb = g_mask + b * Lc;

    for (int kt = 0; kt < 32; kt++) {
        __syncthreads();
        // ---- K,V tile load ----
        const float* Kg = g_K + ((size_t)bh * Lc + kt * 64) * 64;
        const float* Vg = g_V + ((size_t)bh * Lc + kt * 64) * 64;
        #pragma unroll
        for (int it = 0; it < 4; it++) {
            int f = tid + it * 256;    // 1024 float4
            int m = f >> 4, cq = f & 15;
            float4 kv = *(const float4*)(Kg + m * 64 + cq * 4);
            kv.x = f2tf_f(kv.x); kv.y = f2tf_f(kv.y); kv.z = f2tf_f(kv.z); kv.w = f2tf_f(kv.w);
            *(float4*)&Ks[m * QSTR + cq * 4] = kv;
            float4 vv = *(const float4*)(Vg + m * 64 + cq * 4);
            vv.x = f2tf_f(vv.x); vv.y = f2tf_f(vv.y); vv.z = f2tf_f(vv.z); vv.w = f2tf_f(vv.w);
            *(float4*)&Vs[m * VSTR + cq * 4] = vv;
        }
        if (tid < 64) mk[tid] = maskb[kt * 64 + tid] ? -1e30f : 0.f;
        __syncthreads();

        // ---- S = Q . K^T  (warp: 16 rows x 64 cols) ----
        float S[8][4];
        #pragma unroll
        for (int nt = 0; nt < 8; nt++)
            #pragma unroll
            for (int e = 0; e < 4; e++) S[nt][e] = 0.f;
        #pragma unroll
        for (int ks = 0; ks < 64; ks += 8) {
            int r = warpM0 + q;
            uint32_t a0 = __float_as_uint(Qs[r       * QSTR + ks     + tq]);
            uint32_t a1 = __float_as_uint(Qs[(r + 8) * QSTR + ks     + tq]);
            uint32_t a2 = __float_as_uint(Qs[r       * QSTR + ks + 4 + tq]);
            uint32_t a3 = __float_as_uint(Qs[(r + 8) * QSTR + ks + 4 + tq]);
            #pragma unroll
            for (int nt = 0; nt < 8; nt++) {
                int n = nt * 8 + q;
                uint32_t b0 = __float_as_uint(Ks[n * QSTR + ks     + tq]);
                uint32_t b1 = __float_as_uint(Ks[n * QSTR + ks + 4 + tq]);
                mma_tf32(S[nt][0], S[nt][1], S[nt][2], S[nt][3], a0, a1, a2, a3, b0, b1);
            }
        }

        // ---- scale + mask ----
        #pragma unroll
        for (int nt = 0; nt < 8; nt++) {
            float mq0 = mk[nt * 8 + tq * 2];
            float mq1 = mk[nt * 8 + tq * 2 + 1];
            S[nt][0] = S[nt][0] * 0.125f + mq0;
            S[nt][1] = S[nt][1] * 0.125f + mq1;
            S[nt][2] = S[nt][2] * 0.125f + mq0;
            S[nt][3] = S[nt][3] * 0.125f + mq1;
        }

        // ---- online softmax (rows r=warpM0+q and r+8; quad owns a row) ----
        float rm0 = -1e30f, rm1 = -1e30f;
        #pragma unroll
        for (int nt = 0; nt < 8; nt++) {
            rm0 = fmaxf(rm0, fmaxf(S[nt][0], S[nt][1]));
            rm1 = fmaxf(rm1, fmaxf(S[nt][2], S[nt][3]));
        }
        rm0 = fmaxf(rm0, __shfl_xor_sync(0xffffffffu, rm0, 1));
        rm0 = fmaxf(rm0, __shfl_xor_sync(0xffffffffu, rm0, 2));
        rm1 = fmaxf(rm1, __shfl_xor_sync(0xffffffffu, rm1, 1));
        rm1 = fmaxf(rm1, __shfl_xor_sync(0xffffffffu, rm1, 2));
        float mn0 = fmaxf(m0r, rm0);
        float mn1 = fmaxf(m1r, rm1);

        float rs0 = 0.f, rs1 = 0.f;
        #pragma unroll
        for (int nt = 0; nt < 8; nt++) {
            float p0 = (S[nt][0] < -1e29f) ? 0.f : __expf(S[nt][0] - mn0);
            float p1 = (S[nt][1] < -1e29f) ? 0.f : __expf(S[nt][1] - mn0);
            float p2 = (S[nt][2] < -1e29f) ? 0.f : __expf(S[nt][2] - mn1);
            float p3 = (S[nt][3] < -1e29f) ? 0.f : __expf(S[nt][3] - mn1);
            S[nt][0] = p0; S[nt][1] = p1; S[nt][2] = p2; S[nt][3] = p3;
            rs0 += p0 + p1; rs1 += p2 + p3;
        }
        rs0 += __shfl_xor_sync(0xffffffffu, rs0, 1);
        rs0 += __shfl_xor_sync(0xffffffffu, rs0, 2);
        rs1 += __shfl_xor_sync(0xffffffffu, rs1, 1);
        rs1 += __shfl_xor_sync(0xffffffffu, rs1, 2);

        float alpha0 = __expf(m0r - mn0);
        float alpha1 = __expf(m1r - mn1);
        l0r = l0r * alpha0 + rs0;  m0r = mn0;
        l1r = l1r * alpha1 + rs1;  m1r = mn1;

        // rescale O, stage P (tf32-rounded)
        {
            int r = warpM0 + q;
            #pragma unroll
            for (int nt = 0; nt < 8; nt++) {
                O[nt][0] *= alpha0; O[nt][1] *= alpha0;
                O[nt][2] *= alpha1; O[nt][3] *= alpha1;
                float2 p01 = make_float2(f2tf_f(S[nt][0]), f2tf_f(S[nt][1]));
                float2 p23 = make_float2(f2tf_f(S[nt][2]), f2tf_f(S[nt][3]));
                *(float2*)&Ps[r       * QSTR + nt * 8 + tq * 2] = p01;
                *(float2*)&Ps[(r + 8) * QSTR + nt * 8 + tq * 2] = p23;
            }
        }
        __syncthreads();

        // ---- O += P . V ----
        #pragma unroll
        for (int ks = 0; ks < 64; ks += 8) {
            int r = warpM0 + q;
            uint32_t a0 = __float_as_uint(Ps[r       * QSTR + ks     + tq]);
            uint32_t a1 = __float_as_uint(Ps[(r + 8) * QSTR + ks     + tq]);
            uint32_t a2 = __float_as_uint(Ps[r       * QSTR + ks + 4 + tq]);
            uint32_t a3 = __float_as_uint(Ps[(r + 8) * QSTR + ks + 4 + tq]);
            #pragma unroll
            for (int nt = 0; nt < 8; nt++) {
                uint32_t b0 = __float_as_uint(Vs[(ks + tq)     * VSTR + nt * 8 + q]);
                uint32_t b1 = __float_as_uint(Vs[(ks + 4 + tq) * VSTR + nt * 8 + q]);
                mma_tf32(O[nt][0], O[nt][1], O[nt][2], O[nt][3], a0, a1, a2, a3, b0, b1);
            }
        }
    }

    // ---- epilogue: normalize, gate, store token-major ----
    float inv0 = (l0r > 0.f) ? (1.f / l0r) : 0.f;
    float inv1 = (l1r > 0.f) ? (1.f / l1r) : 0.f;
    int r0 = qt * 128 + warpM0 + q;
    size_t tok0 = (size_t)b * Lc + r0;
    size_t tok1 = tok0 + 8;
    #pragma unroll
    for (int nt = 0; nt < 8; nt++) {
        int n = h * 64 + nt * 8 + tq * 2;
        g_AO[tok0 * Dc + n]     = O[nt][0] * inv0 * g_G[tok0 * Dc + n];
        g_AO[tok0 * Dc + n + 1] = O[nt][1] * inv0 * g_G[tok0 * Dc + n + 1];
        g_AO[tok1 * Dc + n]     = O[nt][2] * inv1 * g_G[tok1 * Dc + n];
        g_AO[tok1 * Dc + n + 1] = O[nt][3] * inv1 * g_G[tok1 * Dc + n + 1];
    }
}

// ---------------- TF32 output projection GEMM ------------------------------
__global__ __launch_bounds__(256) void out_gemm_tc(
    const float* __restrict__ Wo, const float* __restrict__ bo,
    float* __restrict__ out)
{
    const int m0 = blockIdx.y * 128;
    const int n0 = blockIdx.x * 64;

    __shared__ float As[128 * GPAD];
    __shared__ float Bs[64  * GPAD];

    const int tid  = threadIdx.x;
    const int warp = tid >> 5;
    const int lane = tid & 31;
    const int q    = lane >> 2;
    const int tq   = lane & 3;
    const int warpM0 = (warp >> 1) * 32;
    const int warpN0 = (warp & 1) * 32;

    float acc[2][4][4];
    #pragma unroll
    for (int mt = 0; mt < 2; mt++)
        #pragma unroll
        for (int nt = 0; nt < 4; nt++)
            #pragma unroll
            for (int e = 0; e < 4; e++) acc[mt][nt][e] = 0.f;

    for (int k0 = 0; k0 < Dc; k0 += 16) {
        __syncthreads();
        #pragma unroll
        for (int i = 0; i < 2; i++) {
            int f = tid + i * 256;
            int m = f >> 2, kq = f & 3;
            float4 v = *(const float4*)(g_AO + (size_t)(m0 + m) * Dc + k0 + kq * 4);
            v.x = f2tf_f(v.x); v.y = f2tf_f(v.y); v.z = f2tf_f(v.z); v.w = f2tf_f(v.w);
            *(float4*)&As[m * GPAD + kq * 4] = v;
        }
        {
            int n = tid >> 2, kq = tid & 3;
            float4 v = *(const float4*)(Wo + (size_t)(n0 + n) * Dc + k0 + kq * 4);
            v.x = f2tf_f(v.x); v.y = f2tf_f(v.y); v.z = f2tf_f(v.z); v.w = f2tf_f(v.w);
            *(float4*)&Bs[n * GPAD + kq * 4] = v;
        }
        __syncthreads();

        #pragma unroll
        for (int ks = 0; ks < 16; ks += 8) {
            uint32_t af[2][4];
            #pragma unroll
            for (int mt = 0; mt < 2; mt++) {
                int r = warpM0 + mt * 16 + q;
                af[mt][0] = __float_as_uint(As[r       * GPAD + ks     + tq]);
                af[mt][1] = __float_as_uint(As[(r + 8) * GPAD + ks     + tq]);
                af[mt][2] = __float_as_uint(As[r       * GPAD + ks + 4 + tq]);
                af[mt][3] = __float_as_uint(As[(r + 8) * GPAD + ks + 4 + tq]);
            }
            #pragma unroll
            for (int nt = 0; nt < 4; nt++) {
                int n = warpN0 + nt * 8 + q;
                uint32_t b0 = __float_as_uint(Bs[n * GPAD + ks     + tq]);
                uint32_t b1 = __float_as_uint(Bs[n * GPAD + ks + 4 + tq]);
                #pragma unroll
                for (int mt = 0; mt < 2; mt++)
                    mma_tf32(acc[mt][nt][0], acc[mt][nt][1], acc[mt][nt][2], acc[mt][nt][3],
                             af[mt][0], af[mt][1], af[mt][2], af[mt][3], b0, b1);
            }
        }
    }

    #pragma unroll
    for (int mt = 0; mt < 2; mt++)
        #pragma unroll
        for (int nt = 0; nt < 4; nt++)
            #pragma unroll
            for (int e = 0; e < 4; e++) {
                int row = m0 + warpM0 + mt * 16 + q + ((e >> 1) ? 8 : 0);
                int col = n0 + warpN0 + nt * 8 + tq * 2 + (e & 1);
                out[(size_t)row * Dc + col] = acc[mt][nt][e] + bo[col];
            }
}

// ---------------- launch ----------------------------------------------------
extern "C" void kernel_launch(void* const* d_in, const int* in_sizes, int n_in,
                              void* d_out, int out_size)
{
    const float* query   = (const float*)d_in[0];
    const float* key_in  = (const float*)d_in[1];
    const float* value   = (const float*)d_in[2];
    const unsigned char* maskraw = (const unsigned char*)d_in[3];
    const float* rope_cos = (const float*)d_in[4];
    const float* rope_sin = (const float*)d_in[5];
    const float* Wq = (const float*)d_in[6];
    const float* bq = (const float*)d_in[7];
    const float* Wk = (const float*)d_in[8];
    const float* bk = (const float*)d_in[9];
    const float* Wv = (const float*)d_in[10];
    const float* bv = (const float*)d_in[11];
    const float* Wg = (const float*)d_in[12];
    const float* bg = (const float*)d_in[13];
    const float* Wo = (const float*)d_in[14];
    const float* bo = (const float*)d_in[15];
    float* out = (float*)d_out;

    (void)in_sizes; (void)n_in; (void)out_size;

    mask_decode_kernel<<<1, 1024>>>(maskraw);

    dim3 pg(Dc / 64, NT / 128, 4);         // (16, 32, 4)
    proj_gemm_tc<<<pg, 256>>>(query, key_in, value,
                              Wq, bq, Wk, bk, Wv, bv, Wg, bg);

    int rope_threads = 2 * BHc * Lc * 32;
    rope_kernel<<<rope_threads / 256, 256>>>(rope_cos, rope_sin);

    cudaFuncSetAttribute(attn_tc_kernel,
                         cudaFuncAttributeMaxDynamicSharedMemorySize, ATTN_SMEM);
    attn_tc_kernel<<<dim3(Lc / 128, BHc), 256, ATTN_SMEM>>>();

    out_gemm_tc<<<dim3(Dc / 64, NT / 128), 256>>>(Wo, bo, out);
}